// round 11
// baseline (speedup 1.0000x reference)
#include <cuda_runtime.h>
#include <math.h>
#include <stdint.h>

#define B 16
#define N 1024
#define BN (B*N)
#define IN 128
#define H 32
#define KC 32
#define KM 16
#define MAXD 128
#define EPSV 1e-15f
#define FULL 0xffffffffu

// ---------------- accumulator slab (atomically accumulated; zeroed per run) --
#define ACC_NUMRW 0                    // [B]
#define ACC_DENRW 16                   // [B]
#define ACC_S00   32                   // [B]
#define ACC_S01   48                   // [B]
#define ACC_S11   64                   // [B]
#define ACC_SAS   80                   // [B]
#define ACC_DENCT 96                   // [B]
#define ACC_SDS   112                  // [B]
#define ACC_VOL   128                  // [B]
#define ACC_SSCT  144                  // [B][32*32]
#define ACC_OA    (ACC_SSCT+B*1024)    // [2][B][256]
#define ACC_SSP   (ACC_OA+2*B*256)     // [2][B][256]
#define ACC_PX    (ACC_SSP+2*B*256)    // [2][B][512]
#define ACC_DENP  (ACC_PX+2*B*512)     // [2][B]
#define ACC_LOSS  (ACC_DENP+2*B)       // [2] main, ortho
#define ACC_TOTAL (ACC_LOSS+2)

__device__ float g_acc[ACC_TOTAL];

// ---------------- scratch ----------------------------------------------------
__device__ float g_xh[BN*H];
__device__ int   g_cols[BN*MAXD];
__device__ int   g_deg[BN];
__device__ float g_srw[BN*2];
__device__ float4 g_ninfo[BN];        // {srw0, srw1, sqct, 0} packed per node
__device__ float g_sct[BN*KC];
__device__ float g_sqct[BN];
__device__ float g_wgap[BN*MAXD];
__device__ float g_wct[BN*MAXD];
__device__ float g_xg[2*BN*H];
__device__ float g_smc[2*BN*KM];
__device__ float g_x2[2*B*KM*H];

__device__ __forceinline__ float wsum(float v){
    #pragma unroll
    for(int o=16;o;o>>=1) v += __shfl_xor_sync(FULL, v, o);
    return v;
}
__device__ __forceinline__ float wsum16(float v){
    #pragma unroll
    for(int o=8;o;o>>=1) v += __shfl_xor_sync(FULL, v, o, 16);
    return v;
}

__global__ void k_init(){
    int i = blockIdx.x*blockDim.x + threadIdx.x;
    if (i < ACC_TOTAL) g_acc[i] = 0.f;
}

// fused: neighbor lists (prefetched float4 + ballot compaction, MLP=8) + vol +
//        xh=x@W1+b1 + rewiring softmax(k=2) + CT softmax(k=32) + scalar partials
__global__ void k_build_soft(const float* __restrict__ adj, const float* __restrict__ x,
                             const float* __restrict__ W1,  const float* __restrict__ b1,
                             const float* __restrict__ Wrw, const float* __restrict__ brw,
                             const float* __restrict__ Wct, const float* __restrict__ bct){
    __shared__ float W1s[IN*H];      // 16 KB
    __shared__ float Wcts[H*KC];     // 4 KB
    __shared__ float svol[8];
    __shared__ float sh[6];
    for (int i = threadIdx.x; i < IN*H; i += blockDim.x) W1s[i] = W1[i];
    for (int i = threadIdx.x; i < H*KC; i += blockDim.x) Wcts[i] = Wct[i];
    if (threadIdx.x < 6) sh[threadIdx.x] = 0.f;
    __syncthreads();

    int wid = (blockIdx.x*blockDim.x + threadIdx.x) >> 5;
    int lane = threadIdx.x & 31;
    int wz = threadIdx.x >> 5;

    // ---- neighbor list: prefetch entire row (MLP=8), then compact ----
    const float4* row = (const float4*)(adj + (size_t)wid * N);
    int* cols = g_cols + (size_t)wid * MAXD;
    float4 v[8];
    #pragma unroll
    for (int i = 0; i < 8; i++) v[i] = row[i*32 + lane];
    int cnt = 0;
    #pragma unroll
    for (int i = 0; i < 8; i++){
        bool n0=v[i].x!=0.f, n1=v[i].y!=0.f, n2=v[i].z!=0.f, n3=v[i].w!=0.f;
        unsigned m0=__ballot_sync(FULL,n0), m1=__ballot_sync(FULL,n1);
        unsigned m2=__ballot_sync(FULL,n2), m3=__ballot_sync(FULL,n3);
        unsigned below = (1u<<lane) - 1u;
        int idx = cnt + __popc(m0&below)+__popc(m1&below)+__popc(m2&below)+__popc(m3&below);
        int col0 = i*128 + lane*4;
        if(n0 && idx<MAXD){ cols[idx]=col0;   idx++; }
        if(n1 && idx<MAXD){ cols[idx]=col0+1; idx++; }
        if(n2 && idx<MAXD){ cols[idx]=col0+2; idx++; }
        if(n3 && idx<MAXD){ cols[idx]=col0+3; idx++; }
        cnt += __popc(m0)+__popc(m1)+__popc(m2)+__popc(m3);
    }
    int deg = cnt < MAXD ? cnt : MAXD;
    if (lane == 0){ g_deg[wid] = deg; svol[wz] = (float)deg; }

    // ---- xh = x @ W1 + b1 (lane = h) ----
    float acc = b1[lane];
    const float* xr = x + (size_t)wid*IN;
    #pragma unroll
    for (int c = 0; c < 4; c++){
        float xv = xr[c*32 + lane];
        #pragma unroll
        for (int j = 0; j < 32; j++)
            acc += __shfl_sync(FULL, xv, j) * W1s[(c*32+j)*H + lane];
    }
    g_xh[wid*H + lane] = acc;

    // ---- rewiring softmax (k=2) ----
    float a0 = wsum(acc*Wrw[lane*2])   + brw[0];
    float a1 = wsum(acc*Wrw[lane*2+1]) + brw[1];
    float mm = fmaxf(a0,a1);
    float e0 = expf(a0-mm), e1 = expf(a1-mm);
    float inv = 1.f/(e0+e1);
    float s0 = e0*inv, s1 = e1*inv;
    if (lane == 0){ g_srw[2*wid]=s0; g_srw[2*wid+1]=s1; }

    // ---- CT softmax (k=32, lane = k) ----
    float a = bct[lane];
    #pragma unroll
    for (int j = 0; j < 32; j++)
        a += __shfl_sync(FULL, acc, j) * Wcts[j*KC + lane];
    float m = a;
    #pragma unroll
    for (int o = 16; o; o >>= 1) m = fmaxf(m, __shfl_xor_sync(FULL, m, o));
    float e = expf(a - m);
    float s = e / wsum(e);
    g_sct[wid*KC + lane] = s;
    float sq = wsum(s*s);
    if (lane == 0){
        g_sqct[wid] = sq;
        g_ninfo[wid] = make_float4(s0, s1, sq, 0.f);
    }

    // ---- per-batch scalar partials ----
    if (lane == 0){
        atomicAdd(&sh[0], (float)deg*(s0*s0 + s1*s1)); // den_rw
        atomicAdd(&sh[1], s0*s0);                      // s00
        atomicAdd(&sh[2], s0*s1);                      // s01
        atomicAdd(&sh[3], s1*s1);                      // s11
        atomicAdd(&sh[4], sq);                         // den_ct
        atomicAdd(&sh[5], (float)deg*sq);              // sds
    }
    __syncthreads();
    int b = blockIdx.x >> 7;
    if (threadIdx.x < 6){
        const int dst[6] = {ACC_DENRW, ACC_S00, ACC_S01, ACC_S11, ACC_DENCT, ACC_SDS};
        atomicAdd(&g_acc[dst[threadIdx.x] + b], sh[threadIdx.x]);
    }
    if (threadIdx.x == 0){
        float vs = 0.f;
        #pragma unroll
        for (int i = 0; i < 8; i++) vs += svol[i];
        atomicAdd(&g_acc[ACC_VOL + b], vs);
    }
}

// S^T S partials from smem tiles (128-node chunks)
__global__ void k_ctpart(){
    int b = blockIdx.x >> 3, c = blockIdx.x & 7;
    int t = threadIdx.x;   // 1024
    __shared__ float S[128][33];
    int n0 = (b*N + c*128)*KC;
    #pragma unroll
    for (int i = 0; i < 4; i++){
        int idx = t + i*1024;
        S[idx>>5][idx&31] = g_sct[n0 + idx];
    }
    __syncthreads();
    int k = t >> 5, l = t & 31;
    float ssv = 0.f;
    #pragma unroll 8
    for (int n = 0; n < 128; n++)
        ssv += S[n][k]*S[n][l];
    atomicAdd(&g_acc[ACC_SSCT + b*1024 + t], ssv);
}

// MEGA-FUSED edge kernel, direct-from-global dot (no staging buffer):
// 8 lanes per edge load the neighbor sct row (one coalesced LDG.128 per 4 edges),
// FMA against register-resident sn slice, 3x shfl_xor segment reduction.
// Weights packed to smem for the both-branch aggregation loop.
__global__ void __launch_bounds__(256, 6)
k_edgeagg(const float* __restrict__ Wr0, const float* __restrict__ br0,
          const float* __restrict__ Wo0, const float* __restrict__ Wm0,
          const float* __restrict__ bm0,
          const float* __restrict__ Wr1, const float* __restrict__ br1,
          const float* __restrict__ Wo1, const float* __restrict__ Wm1,
          const float* __restrict__ bm1){
    __shared__ float4 SN[8][8];                     // sn per warp (32 floats)
    __shared__ float4 WGC[8][32];                   // {wg, wc, mc, 0} per edge
    __shared__ float Wrs[2][H*H], Wos[2][H*H], Wms[2][H*KM];
    __shared__ float shred[4];                      // num, sas, denp0, denp1
    for (int i = threadIdx.x; i < H*H; i += blockDim.x){
        Wrs[0][i] = Wr0[i]; Wrs[1][i] = Wr1[i];
        Wos[0][i] = Wo0[i]; Wos[1][i] = Wo1[i];
    }
    for (int i = threadIdx.x; i < H*KM; i += blockDim.x){
        Wms[0][i] = Wm0[i]; Wms[1][i] = Wm1[i];
    }
    if (threadIdx.x < 4) shred[threadIdx.x] = 0.f;
    __syncthreads();

    int wid = (blockIdx.x*blockDim.x + threadIdx.x) >> 5;
    int lane = threadIdx.x & 31;
    int w = threadIdx.x >> 5;
    float4* wgc = WGC[w];
    int b = wid >> 10, bN = b << 10;
    int deg = g_deg[wid];
    const int* cols = g_cols + wid*MAXD;
    float f_n = g_srw[2*wid];
    float s1n = g_srw[2*wid+1];
    float sn  = g_sct[wid*KC + lane];
    float sqn = g_sqct[wid];
    float invvol = 1.f/(g_acc[ACC_VOL + b] + EPSV);
    float num_acc = 0.f, sas_acc = 0.f;
    float dg_acc = 0.f, dc_acc = 0.f;
    float y_gap = 0.f, y_ct = 0.f;         // lane = h

    // sn -> smem once, then each lane keeps its float4 slice in registers
    ((float*)SN[w])[lane] = sn;
    __syncwarp();
    int r8 = lane >> 3;        // 0..3 : edge-within-group-of-4
    int p8 = lane & 7;         // 0..7 : float4 slot of the row
    float4 sn4r = SN[w][p8];

    for (int j0 = 0; j0 < deg; j0 += 32){
        int tlen = deg - j0; if (tlen > 32) tlen = 32;
        int jl = j0 + lane;
        int mycol = (jl < deg) ? cols[jl] : -1;
        #pragma unroll
        for (int g = 0; g < 8; g++){
            int e = g*4 + r8;                       // edge index in tile
            int mc = __shfl_sync(FULL, mycol, e);
            bool act = mc >= 0;
            float4 v = make_float4(0.f,0.f,0.f,0.f);
            if (act) v = ((const float4*)(g_sct + (size_t)(bN+mc)*KC))[p8];
            float d = v.x*sn4r.x + v.y*sn4r.y + v.z*sn4r.z + v.w*sn4r.w;
            d += __shfl_xor_sync(FULL, d, 1);
            d += __shfl_xor_sync(FULL, d, 2);
            d += __shfl_xor_sync(FULL, d, 4);
            if (p8 == 0){
                float wg = 0.f, wc = 0.f;
                int mcs = 0;
                if (act){
                    float4 ni = g_ninfo[bN + mc];
                    float dd = f_n - ni.x;
                    float q2 = sqn + ni.z - 2.f*d;
                    wg = 1.f - dd*dd;
                    wc = sqrtf(fmaxf(q2, 0.f) + 1e-12f)*invvol;
                    int j = j0 + e;
                    g_wgap[wid*MAXD + j] = wg;
                    g_wct [wid*MAXD + j] = wc;
                    num_acc += f_n*ni.x + s1n*ni.y;
                    sas_acc += d;
                    dg_acc += wg; dc_acc += wc;
                    mcs = mc;
                }
                wgc[e] = make_float4(wg, wc, __int_as_float(mcs), 0.f);
            }
        }
        __syncwarp();
        // both-branch aggregation: broadcast LDS.128 + coalesced LDG, unroll 4
        #pragma unroll 4
        for (int jj = 0; jj < tlen; jj++){
            float4 q = wgc[jj];
            float xv = g_xh[(bN + __float_as_int(q.z))*H + lane];
            y_gap += q.x*xv;
            y_ct  += q.y*xv;
        }
        __syncwarp();
    }
    num_acc = wsum(num_acc);
    sas_acc = wsum(sas_acc);
    float dsum_g = wsum(dg_acc);
    float dsum_c = wsum(dc_acc);

    // lin + pool softmax for both branches
    float xh = g_xh[wid*H + lane];
    float den_g = 0.f, den_c = 0.f;
    #pragma unroll
    for (int br = 0; br < 2; br++){
        float y = br ? y_ct : y_gap;
        const float* brel = br ? br1 : br0;
        const float* bmc  = br ? bm1 : bm0;
        const float* Wr = Wrs[br];
        const float* Wo = Wos[br];
        const float* Wm = Wms[br];
        float acc = brel[lane];
        #pragma unroll
        for (int j = 0; j < 32; j++){
            acc += __shfl_sync(FULL, y,  j) * Wr[j*H + lane];
            acc += __shfl_sync(FULL, xh, j) * Wo[j*H + lane];
        }
        g_xg[br*BN*H + wid*H + lane] = acc;
        float a = (lane < KM) ? bmc[lane] : 0.f;
        #pragma unroll
        for (int j = 0; j < 32; j++){
            float xj = __shfl_sync(FULL, acc, j);
            if (lane < KM) a += xj * Wm[j*KM + lane];
        }
        float mm = a;
        #pragma unroll
        for (int o = 8; o; o >>= 1) mm = fmaxf(mm, __shfl_xor_sync(FULL, mm, o, 16));
        float e = (lane < KM) ? expf(a - mm) : 0.f;
        float es = wsum16(e);
        float s = e/es;
        if (lane < KM) g_smc[br*BN*KM + wid*KM + lane] = s;
        float sq = wsum16(s*s);
        if (br) den_c = sq; else den_g = sq;
    }
    if (lane == 0){
        atomicAdd(&shred[0], num_acc);
        atomicAdd(&shred[1], sas_acc);
        atomicAdd(&shred[2], dsum_g*den_g);
        atomicAdd(&shred[3], dsum_c*den_c);
    }
    __syncthreads();
    if (threadIdx.x < 4){
        int bb = blockIdx.x >> 7;
        const int dst[4] = {ACC_NUMRW, ACC_SAS, ACC_DENP, ACC_DENP + B};
        atomicAdd(&g_acc[dst[threadIdx.x] + bb], shred[threadIdx.x]);
    }
}

// CT losses (ortho over 32x32 S^T S + ct term) + rewiring losses (fused)
__global__ void k_ctfin(){
    int b = blockIdx.x, t = threadIdx.x;   // 1024
    __shared__ float ss[1024], red[1024], nrm_s;
    ss[t] = g_acc[ACC_SSCT + b*1024 + t];
    __syncthreads();
    red[t] = ss[t]*ss[t];
    __syncthreads();
    for (int o = 512; o; o >>= 1){ if (t < o) red[t] += red[t+o]; __syncthreads(); }
    if (t == 0) nrm_s = sqrtf(red[0]);
    __syncthreads();
    int k = t >> 5, l = t & 31;
    float d = ss[t]/nrm_s - ((k == l) ? 0.17677669529663687f : 0.f);
    red[t] = d*d;
    __syncthreads();
    for (int o = 512; o; o >>= 1){ if (t < o) red[t] += red[t+o]; __syncthreads(); }
    if (t == 0){
        float sas = g_acc[ACC_SAS + b];
        float den = g_acc[ACC_DENCT + b] + EPSV;
        float sds = g_acc[ACC_SDS + b];
        float lm = ((sds - sas)/den)/(float)B;
        float lo = sqrtf(red[0])/(float)B;
        float num = g_acc[ACC_NUMRW + b];
        float dnr = g_acc[ACC_DENRW + b] + EPSV;
        float s00 = g_acc[ACC_S00 + b];
        float s01 = g_acc[ACC_S01 + b];
        float s11 = g_acc[ACC_S11 + b];
        float nrm = sqrtf(s00*s00 + 2.f*s01*s01 + s11*s11);
        const float isk = 0.70710678118654752f;
        float d00 = s00/nrm - isk, d01 = s01/nrm, d11 = s11/nrm - isk;
        lm += -(num/dnr)/(float)B;
        lo += sqrtf(d00*d00 + 2.f*d01*d01 + d11*d11)/(float)B;
        atomicAdd(&g_acc[ACC_LOSS],   lm);
        atomicAdd(&g_acc[ACC_LOSS+1], lo);
    }
}

// batch-staged pool: one block = (128-node chunk, batch, branch).
// Full batch smc (64KB) staged in DYNAMIC smem; t16 gathers hit shared memory.
__global__ void k_pool(){
    extern __shared__ float smc_s[];       // N*KM = 16384 floats = 64KB
    __shared__ float st16[128*17];
    int c = blockIdx.x, b = blockIdx.y, br = blockIdx.z;
    int t = threadIdx.x;                   // 1024
    int w = t >> 5, lane = t & 31;
    int bN = b*N;
    const float* smc = g_smc + br*BN*KM;
    {
        float4* dst = (float4*)smc_s;
        const float4* src = (const float4*)(smc + bN*KM);
        #pragma unroll
        for (int i = 0; i < 4; i++) dst[t + i*1024] = src[t + i*1024];
    }
    __syncthreads();
    int half = lane >> 4, l16 = lane & 15;
    #pragma unroll
    for (int q = 0; q < 4; q++){
        int nl = c*128 + w*4 + q;          // local node in batch
        int r = bN + nl;
        int deg = g_deg[r];
        const int* cols = g_cols + r*MAXD;
        const float* w_arr = (br ? g_wct : g_wgap) + r*MAXD;
        float tacc = 0.f;
        #pragma unroll 2
        for (int j = half; j < deg; j += 2)
            tacc += w_arr[j] * smc_s[cols[j]*KM + l16];
        tacc += __shfl_down_sync(FULL, tacc, 16);
        if (lane < KM) st16[(w*4+q)*17 + l16] = tacc;
    }
    __syncthreads();
    int base = (br*B + b)*256;
    int n0 = c*128;
    if (t < 256){
        int k = t >> 4, l = t & 15;
        float oa = 0.f;
        #pragma unroll 4
        for (int n = 0; n < 128; n++)
            oa += smc_s[(n0+n)*KM + k] * st16[n*17 + l];
        atomicAdd(&g_acc[ACC_OA + base + t], oa);
    } else if (t < 512){
        int k = (t-256) >> 4, l = t & 15;
        float ssv = 0.f;
        #pragma unroll 4
        for (int n = 0; n < 128; n++)
            ssv += smc_s[(n0+n)*KM + k] * smc_s[(n0+n)*KM + l];
        atomicAdd(&g_acc[ACC_SSP + base + (t-256)], ssv);
    } else {
        int kk = (t-512) >> 5, h = t & 31;
        float px = 0.f;
        const float* xg = g_xg + br*BN*H + (size_t)(bN + n0)*H;
        #pragma unroll 4
        for (int n = 0; n < 128; n++)
            px += smc_s[(n0+n)*KM + kk] * xg[n*H + h];
        atomicAdd(&g_acc[ACC_PX + (br*B + b)*512 + (t-512)], px);
    }
}

// finalize pool: losses + normalized pooladj + pooled DGC (conv2gap weights)
__global__ void k_poolfin(const float* __restrict__ W2g_rel, const float* __restrict__ b2g,
                          const float* __restrict__ W2g_root){
    int b = blockIdx.x, br = blockIdx.y, t = threadIdx.x;   // 512
    __shared__ float oa[256], ssm[256], px[512], t2[512], pa[256], red[512], nrm_s;
    int base = (br*B + b)*256;
    if (t < 256){ oa[t] = g_acc[ACC_OA + base + t]; ssm[t] = g_acc[ACC_SSP + base + t]; }
    px[t] = g_acc[ACC_PX + (br*B + b)*512 + t];
    __syncthreads();
    red[t] = (t < 256) ? ssm[t]*ssm[t] : 0.f;
    __syncthreads();
    for (int o = 256; o; o >>= 1){ if (t < o) red[t] += red[t+o]; __syncthreads(); }
    if (t == 0) nrm_s = sqrtf(red[0]);
    __syncthreads();
    if (t < 256){
        int k = t >> 4, l = t & 15;
        float d = ssm[t]/nrm_s - ((k == l) ? 0.25f : 0.f);
        red[t] = d*d;
    } else red[t] = 0.f;
    __syncthreads();
    for (int o = 256; o; o >>= 1){ if (t < o) red[t] += red[t+o]; __syncthreads(); }
    if (t == 0){
        float num = 0.f;
        #pragma unroll
        for (int k = 0; k < KM; k++) num += oa[k*KM + k];
        float den = g_acc[ACC_DENP + br*B + b] + EPSV;
        atomicAdd(&g_acc[ACC_LOSS],   -(num/den)/(float)B);
        atomicAdd(&g_acc[ACC_LOSS+1], sqrtf(red[0])/(float)B);
    }
    __shared__ float dsq[KM];
    if (t < KM){
        float rs = 0.f;
        #pragma unroll
        for (int l = 0; l < KM; l++) rs += (l == t) ? 0.f : oa[t*KM + l];
        dsq[t] = sqrtf(rs) + EPSV;
    }
    __syncthreads();
    if (t < 256){
        int k = t >> 4, l = t & 15;
        pa[t] = (k == l) ? 0.f : oa[t]/(dsq[k]*dsq[l]);
    }
    __syncthreads();
    int k = t >> 5, h = t & 31;
    float a = 0.f;
    #pragma unroll
    for (int l = 0; l < KM; l++) a += pa[k*KM + l]*px[l*H + h];
    t2[t] = a;
    __syncthreads();
    float accv = b2g[h];
    #pragma unroll
    for (int j = 0; j < H; j++)
        accv += t2[k*H + j]*W2g_rel[j*H + h] + px[k*H + j]*W2g_root[j*H + h];
    g_x2[br*B*KM*H + b*KM*H + t] = accv;
}

__global__ void k_readout(const float* __restrict__ Wcat, const float* __restrict__ bcat,
                          const float* __restrict__ W2,  const float* __restrict__ b2,
                          const float* __restrict__ W3,  const float* __restrict__ b3,
                          float* __restrict__ out){
    int b = blockIdx.x, h = threadIdx.x;   // 32
    __shared__ float h1[H], h2[H], lg[10];
    float acc = 0.f;
    for (int kk = 0; kk < KM; kk++){
        float z = bcat[h];
        #pragma unroll
        for (int j = 0; j < H; j++) z += g_x2[b*KM*H + kk*H + j]*Wcat[j*H + h];
        #pragma unroll
        for (int j = 0; j < H; j++) z += g_x2[B*KM*H + b*KM*H + kk*H + j]*Wcat[(H+j)*H + h];
        acc += fmaxf(z, 0.f);
    }
    h1[h] = acc; __syncwarp();
    float z2 = b2[h];
    #pragma unroll
    for (int j = 0; j < H; j++) z2 += h1[j]*W2[j*H + h];
    h2[h] = fmaxf(z2, 0.f); __syncwarp();
    if (h < 10){
        float z = b3[h];
        #pragma unroll
        for (int j = 0; j < H; j++) z += h2[j]*W3[j*10 + h];
        lg[h] = z;
    }
    __syncwarp();
    if (h < 10){
        float m = lg[0];
        #pragma unroll
        for (int i = 1; i < 10; i++) m = fmaxf(m, lg[i]);
        float s = 0.f;
        #pragma unroll
        for (int i = 0; i < 10; i++) s += expf(lg[i] - m);
        out[b*10 + h] = lg[h] - m - logf(s);
    }
    if (b == 0 && h == 31){
        out[B*10]     = g_acc[ACC_LOSS];
        out[B*10 + 1] = g_acc[ACC_LOSS+1];
    }
}

extern "C" void kernel_launch(void* const* d_in, const int* in_sizes, int n_in,
                              void* d_out, int out_size){
    const float* x      = (const float*)d_in[0];
    const float* adj    = (const float*)d_in[1];
    const float* W1     = (const float*)d_in[3];
    const float* b1     = (const float*)d_in[4];
    const float* Wrw    = (const float*)d_in[5];
    const float* brw    = (const float*)d_in[6];
    const float* Wg_rel = (const float*)d_in[7];
    const float* bg     = (const float*)d_in[8];
    const float* Wg_root= (const float*)d_in[9];
    const float* Wmcg   = (const float*)d_in[10];
    const float* bmcg   = (const float*)d_in[11];
    const float* W2g_rel= (const float*)d_in[12];
    const float* b2g    = (const float*)d_in[13];
    const float* W2g_root=(const float*)d_in[14];
    const float* Wct    = (const float*)d_in[15];
    const float* bct    = (const float*)d_in[16];
    const float* Wc_rel = (const float*)d_in[17];
    const float* bc     = (const float*)d_in[18];
    const float* Wc_root= (const float*)d_in[19];
    const float* Wmcc   = (const float*)d_in[20];
    const float* bmcc   = (const float*)d_in[21];
    const float* Wcat   = (const float*)d_in[22];
    const float* bcat   = (const float*)d_in[23];
    const float* W2     = (const float*)d_in[24];
    const float* b2     = (const float*)d_in[25];
    const float* W3     = (const float*)d_in[26];
    const float* b3     = (const float*)d_in[27];
    float* out = (float*)d_out;

    cudaFuncSetAttribute(k_pool, cudaFuncAttributeMaxDynamicSharedMemorySize, 65536);

    k_init<<<(ACC_TOTAL+511)/512, 512>>>();
    k_build_soft<<<BN/8, 256>>>(adj, x, W1, b1, Wrw, brw, Wct, bct);
    k_ctpart<<<B*8, 1024>>>();
    k_edgeagg<<<BN/8, 256>>>(Wg_rel, bg, Wg_root, Wmcg, bmcg,
                             Wc_rel, bc, Wc_root, Wmcc, bmcc);
    k_ctfin<<<B, 1024>>>();
    k_pool<<<dim3(8, B, 2), 1024, 65536>>>();
    k_poolfin<<<dim3(B, 2), 512>>>(W2g_rel, b2g, W2g_root);
    k_readout<<<B, 32>>>(Wcat, bcat, W2, b2, W3, b3, out);

    (void)in_sizes; (void)n_in; (void)out_size;
}

// round 12
// speedup vs baseline: 1.0894x; 1.0894x over previous
#include <cuda_runtime.h>
#include <math.h>
#include <stdint.h>

#define B 16
#define N 1024
#define BN (B*N)
#define IN 128
#define H 32
#define KC 32
#define KM 16
#define MAXD 128
#define EPSV 1e-15f
#define FULL 0xffffffffu

// ---------------- accumulator slab (atomically accumulated; zeroed per run) --
#define ACC_NUMRW 0                    // [B]
#define ACC_DENRW 16                   // [B]
#define ACC_S00   32                   // [B]
#define ACC_S01   48                   // [B]
#define ACC_S11   64                   // [B]
#define ACC_SAS   80                   // [B]
#define ACC_DENCT 96                   // [B]
#define ACC_SDS   112                  // [B]
#define ACC_VOL   128                  // [B]
#define ACC_SSCT  144                  // [B][32*32]
#define ACC_OA    (ACC_SSCT+B*1024)    // [2][B][256]
#define ACC_SSP   (ACC_OA+2*B*256)     // [2][B][256]
#define ACC_PX    (ACC_SSP+2*B*256)    // [2][B][512]
#define ACC_DENP  (ACC_PX+2*B*512)     // [2][B]
#define ACC_LOSS  (ACC_DENP+2*B)       // [2] main, ortho
#define ACC_TOTAL (ACC_LOSS+2)

__device__ float g_acc[ACC_TOTAL];

// ---------------- scratch ----------------------------------------------------
__device__ float g_xh[BN*H];
__device__ int   g_cols[BN*MAXD];
__device__ int   g_deg[BN];
__device__ float g_srw[BN*2];
__device__ float4 g_ninfo[BN];        // {srw0, srw1, sqct, 0} packed per node
__device__ float g_sct[BN*KC];
__device__ float g_sqct[BN];
__device__ float g_wgap[BN*MAXD];
__device__ float g_wct[BN*MAXD];
__device__ float g_xg[2*BN*H];
__device__ float g_smc[2*BN*KM];
__device__ float g_x2[2*B*KM*H];

__device__ __forceinline__ float wsum(float v){
    #pragma unroll
    for(int o=16;o;o>>=1) v += __shfl_xor_sync(FULL, v, o);
    return v;
}
__device__ __forceinline__ float wsum16(float v){
    #pragma unroll
    for(int o=8;o;o>>=1) v += __shfl_xor_sync(FULL, v, o, 16);
    return v;
}

__global__ void k_init(){
    int i = blockIdx.x*blockDim.x + threadIdx.x;
    if (i < ACC_TOTAL) g_acc[i] = 0.f;
}

// fused: neighbor lists (prefetched float4 + ballot compaction, MLP=8) + vol +
//        xh=x@W1+b1 + rewiring softmax(k=2) + CT softmax(k=32) + scalar partials
__global__ void k_build_soft(const float* __restrict__ adj, const float* __restrict__ x,
                             const float* __restrict__ W1,  const float* __restrict__ b1,
                             const float* __restrict__ Wrw, const float* __restrict__ brw,
                             const float* __restrict__ Wct, const float* __restrict__ bct){
    __shared__ float W1s[IN*H];      // 16 KB
    __shared__ float Wcts[H*KC];     // 4 KB
    __shared__ float svol[8];
    __shared__ float sh[6];
    for (int i = threadIdx.x; i < IN*H; i += blockDim.x) W1s[i] = W1[i];
    for (int i = threadIdx.x; i < H*KC; i += blockDim.x) Wcts[i] = Wct[i];
    if (threadIdx.x < 6) sh[threadIdx.x] = 0.f;
    __syncthreads();

    int wid = (blockIdx.x*blockDim.x + threadIdx.x) >> 5;
    int lane = threadIdx.x & 31;
    int wz = threadIdx.x >> 5;

    // ---- neighbor list: prefetch entire row (MLP=8), then compact ----
    const float4* row = (const float4*)(adj + (size_t)wid * N);
    int* cols = g_cols + (size_t)wid * MAXD;
    float4 v[8];
    #pragma unroll
    for (int i = 0; i < 8; i++) v[i] = row[i*32 + lane];
    int cnt = 0;
    #pragma unroll
    for (int i = 0; i < 8; i++){
        bool n0=v[i].x!=0.f, n1=v[i].y!=0.f, n2=v[i].z!=0.f, n3=v[i].w!=0.f;
        unsigned m0=__ballot_sync(FULL,n0), m1=__ballot_sync(FULL,n1);
        unsigned m2=__ballot_sync(FULL,n2), m3=__ballot_sync(FULL,n3);
        unsigned below = (1u<<lane) - 1u;
        int idx = cnt + __popc(m0&below)+__popc(m1&below)+__popc(m2&below)+__popc(m3&below);
        int col0 = i*128 + lane*4;
        if(n0 && idx<MAXD){ cols[idx]=col0;   idx++; }
        if(n1 && idx<MAXD){ cols[idx]=col0+1; idx++; }
        if(n2 && idx<MAXD){ cols[idx]=col0+2; idx++; }
        if(n3 && idx<MAXD){ cols[idx]=col0+3; idx++; }
        cnt += __popc(m0)+__popc(m1)+__popc(m2)+__popc(m3);
    }
    int deg = cnt < MAXD ? cnt : MAXD;
    if (lane == 0){ g_deg[wid] = deg; svol[wz] = (float)deg; }

    // ---- xh = x @ W1 + b1 (lane = h) ----
    float acc = b1[lane];
    const float* xr = x + (size_t)wid*IN;
    #pragma unroll
    for (int c = 0; c < 4; c++){
        float xv = xr[c*32 + lane];
        #pragma unroll
        for (int j = 0; j < 32; j++)
            acc += __shfl_sync(FULL, xv, j) * W1s[(c*32+j)*H + lane];
    }
    g_xh[wid*H + lane] = acc;

    // ---- rewiring softmax (k=2) ----
    float a0 = wsum(acc*Wrw[lane*2])   + brw[0];
    float a1 = wsum(acc*Wrw[lane*2+1]) + brw[1];
    float mm = fmaxf(a0,a1);
    float e0 = expf(a0-mm), e1 = expf(a1-mm);
    float inv = 1.f/(e0+e1);
    float s0 = e0*inv, s1 = e1*inv;
    if (lane == 0){ g_srw[2*wid]=s0; g_srw[2*wid+1]=s1; }

    // ---- CT softmax (k=32, lane = k) ----
    float a = bct[lane];
    #pragma unroll
    for (int j = 0; j < 32; j++)
        a += __shfl_sync(FULL, acc, j) * Wcts[j*KC + lane];
    float m = a;
    #pragma unroll
    for (int o = 16; o; o >>= 1) m = fmaxf(m, __shfl_xor_sync(FULL, m, o));
    float e = expf(a - m);
    float s = e / wsum(e);
    g_sct[wid*KC + lane] = s;
    float sq = wsum(s*s);
    if (lane == 0){
        g_sqct[wid] = sq;
        g_ninfo[wid] = make_float4(s0, s1, sq, 0.f);
    }

    // ---- per-batch scalar partials ----
    if (lane == 0){
        atomicAdd(&sh[0], (float)deg*(s0*s0 + s1*s1)); // den_rw
        atomicAdd(&sh[1], s0*s0);                      // s00
        atomicAdd(&sh[2], s0*s1);                      // s01
        atomicAdd(&sh[3], s1*s1);                      // s11
        atomicAdd(&sh[4], sq);                         // den_ct
        atomicAdd(&sh[5], (float)deg*sq);              // sds
    }
    __syncthreads();
    int b = blockIdx.x >> 7;
    if (threadIdx.x < 6){
        const int dst[6] = {ACC_DENRW, ACC_S00, ACC_S01, ACC_S11, ACC_DENCT, ACC_SDS};
        atomicAdd(&g_acc[dst[threadIdx.x] + b], sh[threadIdx.x]);
    }
    if (threadIdx.x == 0){
        float vs = 0.f;
        #pragma unroll
        for (int i = 0; i < 8; i++) vs += svol[i];
        atomicAdd(&g_acc[ACC_VOL + b], vs);
    }
}

// S^T S partials from smem tiles (128-node chunks)
__global__ void k_ctpart(){
    int b = blockIdx.x >> 3, c = blockIdx.x & 7;
    int t = threadIdx.x;   // 1024
    __shared__ float S[128][33];
    int n0 = (b*N + c*128)*KC;
    #pragma unroll
    for (int i = 0; i < 4; i++){
        int idx = t + i*1024;
        S[idx>>5][idx&31] = g_sct[n0 + idx];
    }
    __syncthreads();
    int k = t >> 5, l = t & 31;
    float ssv = 0.f;
    #pragma unroll 8
    for (int n = 0; n < 128; n++)
        ssv += S[n][k]*S[n][l];
    atomicAdd(&g_acc[ACC_SSCT + b*1024 + t], ssv);
}

// MEGA-FUSED edge kernel (R10 design: 16-edge staged subtiles), weights read
// directly from global in the tail (L1-hit broadcast) => smem ~22KB, occ 75%.
__global__ void __launch_bounds__(256, 6)
k_edgeagg(const float* __restrict__ Wr0, const float* __restrict__ br0,
          const float* __restrict__ Wo0, const float* __restrict__ Wm0,
          const float* __restrict__ bm0,
          const float* __restrict__ Wr1, const float* __restrict__ br1,
          const float* __restrict__ Wo1, const float* __restrict__ Wm1,
          const float* __restrict__ bm1){
    __shared__ float  S[8*16*36];                   // 18 KB row staging
    __shared__ float4 SN[8][8];                     // sn per warp (32 floats)
    __shared__ float4 WGC[8][16];                   // {wg, wc, mc, 0} per edge
    __shared__ float shred[4];                      // num, sas, denp0, denp1
    if (threadIdx.x < 4) shred[threadIdx.x] = 0.f;
    __syncthreads();

    int wid = (blockIdx.x*blockDim.x + threadIdx.x) >> 5;
    int lane = threadIdx.x & 31;
    int w = threadIdx.x >> 5;
    float* Sw = S + w*16*36;
    float4* wgc = WGC[w];
    int b = wid >> 10, bN = b << 10;
    int deg = g_deg[wid];
    const int* cols = g_cols + wid*MAXD;
    float f_n = g_srw[2*wid];
    float s1n = g_srw[2*wid+1];
    float sn  = g_sct[wid*KC + lane];
    float sqn = g_sqct[wid];
    float invvol = 1.f/(g_acc[ACC_VOL + b] + EPSV);
    float num_acc = 0.f, sas_acc = 0.f;
    float dg_acc = 0.f, dc_acc = 0.f;
    float y_gap = 0.f, y_ct = 0.f;         // lane = h

    // stage sn into smem once (read back as float4)
    ((float*)SN[w])[lane] = sn;
    __syncwarp();

    int r8 = lane >> 3;        // 0..3 : row group
    int p8 = lane & 7;         // 0..7 : float4 slot
    int eh = lane & 15;        // edge within subtile
    int half = lane >> 4;      // which 16 elements of the dot

    for (int j0 = 0; j0 < deg; j0 += 16){
        int tlen = deg - j0; if (tlen > 16) tlen = 16;
        // cooperative vectorized staging of up to 16 neighbor sct rows
        #pragma unroll
        for (int g = 0; g < 4; g++){
            int e = g*4 + r8;
            int j = j0 + e;
            if (j < deg){
                int rm = bN + cols[j];
                float4 v = ((const float4*)(g_sct + (size_t)rm*KC))[p8];
                ((float4*)(Sw + e*36))[p8] = v;
            }
        }
        __syncwarp();
        int j = j0 + eh;
        bool act = j < deg;
        int mc = act ? cols[j] : 0;
        const float4* row4 = (const float4*)(Sw + eh*36) + half*4;
        const float4* sn4  = SN[w] + half*4;
        float dA = 0.f, dB = 0.f;
        #pragma unroll
        for (int q = 0; q < 2; q++){
            float4 va = row4[2*q],   sa = sn4[2*q];
            float4 vb = row4[2*q+1], sb = sn4[2*q+1];
            dA += va.x*sa.x + va.y*sa.y + va.z*sa.z + va.w*sa.w;
            dB += vb.x*sb.x + vb.y*sb.y + vb.z*sb.z + vb.w*sb.w;
        }
        float dh = dA + dB;
        float dot = dh + __shfl_xor_sync(FULL, dh, 16);
        float wg = 0.f, wc = 0.f;
        if (act && half == 0){
            float4 ni = g_ninfo[bN + mc];
            float d = f_n - ni.x;
            float q2 = sqn + ni.z - 2.f*dot;
            wg = 1.f - d*d;
            wc = sqrtf(fmaxf(q2, 0.f) + 1e-12f)*invvol;
            g_wgap[wid*MAXD + j] = wg;
            g_wct [wid*MAXD + j] = wc;
            num_acc += f_n*ni.x + s1n*ni.y;
            sas_acc += dot;
        }
        dg_acc += wg; dc_acc += wc;
        if (half == 0) wgc[eh] = make_float4(wg, wc, __int_as_float(mc), 0.f);
        __syncwarp();
        // both-branch aggregation: broadcast LDS.128 + coalesced LDG, unroll 4
        #pragma unroll 4
        for (int jj = 0; jj < tlen; jj++){
            float4 q = wgc[jj];
            float xv = g_xh[(bN + __float_as_int(q.z))*H + lane];
            y_gap += q.x*xv;
            y_ct  += q.y*xv;
        }
        __syncwarp();
    }
    num_acc = wsum(num_acc);
    sas_acc = wsum(sas_acc);
    float dsum_g = wsum(dg_acc);
    float dsum_c = wsum(dc_acc);

    // lin + pool softmax for both branches (weights from global; L1-hit broadcast)
    float xh = g_xh[wid*H + lane];
    float den_g = 0.f, den_c = 0.f;
    #pragma unroll
    for (int br = 0; br < 2; br++){
        float y = br ? y_ct : y_gap;
        const float* brel = br ? br1 : br0;
        const float* bmc  = br ? bm1 : bm0;
        const float* Wr = br ? Wr1 : Wr0;
        const float* Wo = br ? Wo1 : Wo0;
        const float* Wm = br ? Wm1 : Wm0;
        float acc = brel[lane];
        #pragma unroll
        for (int j = 0; j < 32; j++){
            acc += __shfl_sync(FULL, y,  j) * Wr[j*H + lane];
            acc += __shfl_sync(FULL, xh, j) * Wo[j*H + lane];
        }
        g_xg[br*BN*H + wid*H + lane] = acc;
        float a = (lane < KM) ? bmc[lane] : 0.f;
        #pragma unroll
        for (int j = 0; j < 32; j++){
            float xj = __shfl_sync(FULL, acc, j);
            if (lane < KM) a += xj * Wm[j*KM + lane];
        }
        float mm = a;
        #pragma unroll
        for (int o = 8; o; o >>= 1) mm = fmaxf(mm, __shfl_xor_sync(FULL, mm, o, 16));
        float e = (lane < KM) ? expf(a - mm) : 0.f;
        float es = wsum16(e);
        float s = e/es;
        if (lane < KM) g_smc[br*BN*KM + wid*KM + lane] = s;
        float sq = wsum16(s*s);
        if (br) den_c = sq; else den_g = sq;
    }
    if (lane == 0){
        atomicAdd(&shred[0], num_acc);
        atomicAdd(&shred[1], sas_acc);
        atomicAdd(&shred[2], dsum_g*den_g);
        atomicAdd(&shred[3], dsum_c*den_c);
    }
    __syncthreads();
    if (threadIdx.x < 4){
        int bb = blockIdx.x >> 7;
        const int dst[4] = {ACC_NUMRW, ACC_SAS, ACC_DENP, ACC_DENP + B};
        atomicAdd(&g_acc[dst[threadIdx.x] + bb], shred[threadIdx.x]);
    }
}

// CT losses (ortho over 32x32 S^T S + ct term) + rewiring losses (fused)
__global__ void k_ctfin(){
    int b = blockIdx.x, t = threadIdx.x;   // 1024
    __shared__ float ss[1024], red[1024], nrm_s;
    ss[t] = g_acc[ACC_SSCT + b*1024 + t];
    __syncthreads();
    red[t] = ss[t]*ss[t];
    __syncthreads();
    for (int o = 512; o; o >>= 1){ if (t < o) red[t] += red[t+o]; __syncthreads(); }
    if (t == 0) nrm_s = sqrtf(red[0]);
    __syncthreads();
    int k = t >> 5, l = t & 31;
    float d = ss[t]/nrm_s - ((k == l) ? 0.17677669529663687f : 0.f);
    red[t] = d*d;
    __syncthreads();
    for (int o = 512; o; o >>= 1){ if (t < o) red[t] += red[t+o]; __syncthreads(); }
    if (t == 0){
        float sas = g_acc[ACC_SAS + b];
        float den = g_acc[ACC_DENCT + b] + EPSV;
        float sds = g_acc[ACC_SDS + b];
        float lm = ((sds - sas)/den)/(float)B;
        float lo = sqrtf(red[0])/(float)B;
        float num = g_acc[ACC_NUMRW + b];
        float dnr = g_acc[ACC_DENRW + b] + EPSV;
        float s00 = g_acc[ACC_S00 + b];
        float s01 = g_acc[ACC_S01 + b];
        float s11 = g_acc[ACC_S11 + b];
        float nrm = sqrtf(s00*s00 + 2.f*s01*s01 + s11*s11);
        const float isk = 0.70710678118654752f;
        float d00 = s00/nrm - isk, d01 = s01/nrm, d11 = s11/nrm - isk;
        lm += -(num/dnr)/(float)B;
        lo += sqrtf(d00*d00 + 2.f*d01*d01 + d11*d11)/(float)B;
        atomicAdd(&g_acc[ACC_LOSS],   lm);
        atomicAdd(&g_acc[ACC_LOSS+1], lo);
    }
}

// batch-staged pool: one block = (128-node chunk, batch, branch).
// Full batch smc (64KB) staged in DYNAMIC smem; t16 gathers hit shared memory.
__global__ void k_pool(){
    extern __shared__ float smc_s[];       // N*KM = 16384 floats = 64KB
    __shared__ float st16[128*17];
    int c = blockIdx.x, b = blockIdx.y, br = blockIdx.z;
    int t = threadIdx.x;                   // 1024
    int w = t >> 5, lane = t & 31;
    int bN = b*N;
    const float* smc = g_smc + br*BN*KM;
    {
        float4* dst = (float4*)smc_s;
        const float4* src = (const float4*)(smc + bN*KM);
        #pragma unroll
        for (int i = 0; i < 4; i++) dst[t + i*1024] = src[t + i*1024];
    }
    __syncthreads();
    int half = lane >> 4, l16 = lane & 15;
    #pragma unroll
    for (int q = 0; q < 4; q++){
        int nl = c*128 + w*4 + q;          // local node in batch
        int r = bN + nl;
        int deg = g_deg[r];
        const int* cols = g_cols + r*MAXD;
        const float* w_arr = (br ? g_wct : g_wgap) + r*MAXD;
        float tacc = 0.f;
        #pragma unroll 2
        for (int j = half; j < deg; j += 2)
            tacc += w_arr[j] * smc_s[cols[j]*KM + l16];
        tacc += __shfl_down_sync(FULL, tacc, 16);
        if (lane < KM) st16[(w*4+q)*17 + l16] = tacc;
    }
    __syncthreads();
    int base = (br*B + b)*256;
    int n0 = c*128;
    if (t < 256){
        int k = t >> 4, l = t & 15;
        float oa = 0.f;
        #pragma unroll 4
        for (int n = 0; n < 128; n++)
            oa += smc_s[(n0+n)*KM + k] * st16[n*17 + l];
        atomicAdd(&g_acc[ACC_OA + base + t], oa);
    } else if (t < 512){
        int k = (t-256) >> 4, l = t & 15;
        float ssv = 0.f;
        #pragma unroll 4
        for (int n = 0; n < 128; n++)
            ssv += smc_s[(n0+n)*KM + k] * smc_s[(n0+n)*KM + l];
        atomicAdd(&g_acc[ACC_SSP + base + (t-256)], ssv);
    } else {
        int kk = (t-512) >> 5, h = t & 31;
        float px = 0.f;
        const float* xg = g_xg + br*BN*H + (size_t)(bN + n0)*H;
        #pragma unroll 4
        for (int n = 0; n < 128; n++)
            px += smc_s[(n0+n)*KM + kk] * xg[n*H + h];
        atomicAdd(&g_acc[ACC_PX + (br*B + b)*512 + (t-512)], px);
    }
}

// finalize pool: losses + normalized pooladj + pooled DGC (conv2gap weights)
__global__ void k_poolfin(const float* __restrict__ W2g_rel, const float* __restrict__ b2g,
                          const float* __restrict__ W2g_root){
    int b = blockIdx.x, br = blockIdx.y, t = threadIdx.x;   // 512
    __shared__ float oa[256], ssm[256], px[512], t2[512], pa[256], red[512], nrm_s;
    int base = (br*B + b)*256;
    if (t < 256){ oa[t] = g_acc[ACC_OA + base + t]; ssm[t] = g_acc[ACC_SSP + base + t]; }
    px[t] = g_acc[ACC_PX + (br*B + b)*512 + t];
    __syncthreads();
    red[t] = (t < 256) ? ssm[t]*ssm[t] : 0.f;
    __syncthreads();
    for (int o = 256; o; o >>= 1){ if (t < o) red[t] += red[t+o]; __syncthreads(); }
    if (t == 0) nrm_s = sqrtf(red[0]);
    __syncthreads();
    if (t < 256){
        int k = t >> 4, l = t & 15;
        float d = ssm[t]/nrm_s - ((k == l) ? 0.25f : 0.f);
        red[t] = d*d;
    } else red[t] = 0.f;
    __syncthreads();
    for (int o = 256; o; o >>= 1){ if (t < o) red[t] += red[t+o]; __syncthreads(); }
    if (t == 0){
        float num = 0.f;
        #pragma unroll
        for (int k = 0; k < KM; k++) num += oa[k*KM + k];
        float den = g_acc[ACC_DENP + br*B + b] + EPSV;
        atomicAdd(&g_acc[ACC_LOSS],   -(num/den)/(float)B);
        atomicAdd(&g_acc[ACC_LOSS+1], sqrtf(red[0])/(float)B);
    }
    __shared__ float dsq[KM];
    if (t < KM){
        float rs = 0.f;
        #pragma unroll
        for (int l = 0; l < KM; l++) rs += (l == t) ? 0.f : oa[t*KM + l];
        dsq[t] = sqrtf(rs) + EPSV;
    }
    __syncthreads();
    if (t < 256){
        int k = t >> 4, l = t & 15;
        pa[t] = (k == l) ? 0.f : oa[t]/(dsq[k]*dsq[l]);
    }
    __syncthreads();
    int k = t >> 5, h = t & 31;
    float a = 0.f;
    #pragma unroll
    for (int l = 0; l < KM; l++) a += pa[k*KM + l]*px[l*H + h];
    t2[t] = a;
    __syncthreads();
    float accv = b2g[h];
    #pragma unroll
    for (int j = 0; j < H; j++)
        accv += t2[k*H + j]*W2g_rel[j*H + h] + px[k*H + j]*W2g_root[j*H + h];
    g_x2[br*B*KM*H + b*KM*H + t] = accv;
}

__global__ void k_readout(const float* __restrict__ Wcat, const float* __restrict__ bcat,
                          const float* __restrict__ W2,  const float* __restrict__ b2,
                          const float* __restrict__ W3,  const float* __restrict__ b3,
                          float* __restrict__ out){
    int b = blockIdx.x, h = threadIdx.x;   // 32
    __shared__ float h1[H], h2[H], lg[10];
    float acc = 0.f;
    for (int kk = 0; kk < KM; kk++){
        float z = bcat[h];
        #pragma unroll
        for (int j = 0; j < H; j++) z += g_x2[b*KM*H + kk*H + j]*Wcat[j*H + h];
        #pragma unroll
        for (int j = 0; j < H; j++) z += g_x2[B*KM*H + b*KM*H + kk*H + j]*Wcat[(H+j)*H + h];
        acc += fmaxf(z, 0.f);
    }
    h1[h] = acc; __syncwarp();
    float z2 = b2[h];
    #pragma unroll
    for (int j = 0; j < H; j++) z2 += h1[j]*W2[j*H + h];
    h2[h] = fmaxf(z2, 0.f); __syncwarp();
    if (h < 10){
        float z = b3[h];
        #pragma unroll
        for (int j = 0; j < H; j++) z += h2[j]*W3[j*10 + h];
        lg[h] = z;
    }
    __syncwarp();
    if (h < 10){
        float m = lg[0];
        #pragma unroll
        for (int i = 1; i < 10; i++) m = fmaxf(m, lg[i]);
        float s = 0.f;
        #pragma unroll
        for (int i = 0; i < 10; i++) s += expf(lg[i] - m);
        out[b*10 + h] = lg[h] - m - logf(s);
    }
    if (b == 0 && h == 31){
        out[B*10]     = g_acc[ACC_LOSS];
        out[B*10 + 1] = g_acc[ACC_LOSS+1];
    }
}

extern "C" void kernel_launch(void* const* d_in, const int* in_sizes, int n_in,
                              void* d_out, int out_size){
    const float* x      = (const float*)d_in[0];
    const float* adj    = (const float*)d_in[1];
    const float* W1     = (const float*)d_in[3];
    const float* b1     = (const float*)d_in[4];
    const float* Wrw    = (const float*)d_in[5];
    const float* brw    = (const float*)d_in[6];
    const float* Wg_rel = (const float*)d_in[7];
    const float* bg     = (const float*)d_in[8];
    const float* Wg_root= (const float*)d_in[9];
    const float* Wmcg   = (const float*)d_in[10];
    const float* bmcg   = (const float*)d_in[11];
    const float* W2g_rel= (const float*)d_in[12];
    const float* b2g    = (const float*)d_in[13];
    const float* W2g_root=(const float*)d_in[14];
    const float* Wct    = (const float*)d_in[15];
    const float* bct    = (const float*)d_in[16];
    const float* Wc_rel = (const float*)d_in[17];
    const float* bc     = (const float*)d_in[18];
    const float* Wc_root= (const float*)d_in[19];
    const float* Wmcc   = (const float*)d_in[20];
    const float* bmcc   = (const float*)d_in[21];
    const float* Wcat   = (const float*)d_in[22];
    const float* bcat   = (const float*)d_in[23];
    const float* W2     = (const float*)d_in[24];
    const float* b2     = (const float*)d_in[25];
    const float* W3     = (const float*)d_in[26];
    const float* b3     = (const float*)d_in[27];
    float* out = (float*)d_out;

    cudaFuncSetAttribute(k_pool, cudaFuncAttributeMaxDynamicSharedMemorySize, 65536);

    k_init<<<(ACC_TOTAL+511)/512, 512>>>();
    k_build_soft<<<BN/8, 256>>>(adj, x, W1, b1, Wrw, brw, Wct, bct);
    k_ctpart<<<B*8, 1024>>>();
    k_edgeagg<<<BN/8, 256>>>(Wg_rel, bg, Wg_root, Wmcg, bmcg,
                             Wc_rel, bc, Wc_root, Wmcc, bmcc);
    k_ctfin<<<B, 1024>>>();
    k_pool<<<dim3(8, B, 2), 1024, 65536>>>();
    k_poolfin<<<dim3(B, 2), 512>>>(W2g_rel, b2g, W2g_root);
    k_readout<<<B, 32>>>(Wcat, bcat, W2, b2, W3, b3, out);

    (void)in_sizes; (void)n_in; (void)out_size;
}